// round 15
// baseline (speedup 1.0000x reference)
#include <cuda_runtime.h>
#include <math.h>

#define NB   64
#define IMG  384
#define CIN  3
#define PS   16
#define DM   96
#define DS   16
#define DI   96
#define HP   24
#define NT   576
#define NR   (NB*NT)          // 36864 token rows
#define NPIX (NB*CIN*IMG*IMG) // 28311552
#define NBLUR (192*144)       // blur tile blocks

// ---------------- scratch (device globals; no allocs allowed) ----------------
static __device__ float  g_xl[NPIX];        // preprocessed image, PATCH-MAJOR [gp][768]
static __device__ float  g_WpeT[768*96];    // transposed patch weights [k][d]
static __device__ float  g_tokens[NR*DM];
static __device__ float  g_vis[NR];
static __device__ float  g_gate[NR*DM];
static __device__ float  g_xin[NR*DI];      // pre-conv x branch
static __device__ float  g_zg[NR*DI];       // silu(z)*vis
static __device__ float  g_bc[NR*32];       // B(16) | C(16)
static __device__ float2 g_meta[NR*DI];     // {dt, xs}
static __device__ float  g_yg[NR*DI];       // y_raw = yp + D*xs  (zg applied in rg2)

__device__ __forceinline__ float sigm_(float x){ return 1.f/(1.f+__expf(-x)); }
__device__ __forceinline__ float silu_(float x){ return x/(1.f+__expf(-x)); }
__device__ __forceinline__ float softplus_(float x){ return (x>20.f)? x : __logf(1.f+__expf(x)); }

// ---- packed fp32x2 helpers (Blackwell FFMA2 path, PTX-only) ----
typedef unsigned long long u64;
__device__ __forceinline__ void ffma2(u64 &d, u64 a, u64 b){
    asm("fma.rn.f32x2 %0, %1, %2, %3;" : "=l"(d) : "l"(a), "l"(b), "l"(d));
}
__device__ __forceinline__ u64 pack2(float x, float y){
    u64 r;
    asm("mov.b64 %0, {%1, %2};" : "=l"(r) : "r"(__float_as_uint(x)), "r"(__float_as_uint(y)));
    return r;
}
__device__ __forceinline__ float2 unpack2(u64 v){
    unsigned lo, hi;
    asm("mov.b64 {%0, %1}, %2;" : "=r"(lo), "=r"(hi) : "l"(v));
    return make_float2(__uint_as_float(lo), __uint_as_float(hi));
}

// ---------------- 1) fused 5x5 box blur + log contrast (+W_pe transpose blocks) ----------------
__global__ void k_blur(const float* __restrict__ x, const float* __restrict__ Wpe){
    if (blockIdx.x >= NBLUR){
        int base = (blockIdx.x - NBLUR)*2560 + threadIdx.x;
        for (int idx = base; idx < 768*96 && idx < base + 2560; idx += 256){
            int k = idx/96, d = idx%96;
            g_WpeT[idx] = Wpe[d*768 + k];
        }
        return;
    }
    __shared__ float in_s[36][37];
    __shared__ float hs[36][33];
    int tid = threadIdx.x;                   // 256
    int p = blockIdx.x / 144;
    int t = blockIdx.x % 144;
    int y0 = (t/12)*32, x0 = (t%12)*32;
    const float* xp = x + (size_t)p*IMG*IMG;

    for (int idx=tid; idx<36*36; idx+=256){
        int r = idx/36, cc = idx%36;
        int yy = y0-2+r, xx = x0-2+cc;
        in_s[r][cc] = (yy>=0 && yy<IMG && xx>=0 && xx<IMG) ? xp[yy*IMG+xx] : 0.f;
    }
    __syncthreads();
    for (int idx=tid; idx<36*32; idx+=256){
        int r = idx/32, j = idx%32;
        hs[r][j] = in_s[r][j]+in_s[r][j+1]+in_s[r][j+2]+in_s[r][j+3]+in_s[r][j+4];
    }
    __syncthreads();
    int b = p/3, c = p%3;
    for (int idx=tid; idx<32*32; idx+=256){
        int r = idx/32, j = idx%32;
        float bl = (hs[r][j]+hs[r+1][j]+hs[r+2][j]+hs[r+3][j]+hs[r+4][j])*(1.f/25.f);
        float xv = in_s[r+2][j+2];
        float v  = __logf(1.f + fmaxf(xv,0.f)) - __logf(1.f + fmaxf(bl,0.f));
        int yy = y0+r, xx = x0+j;
        int gp  = b*NT + (yy>>4)*HP + (xx>>4);
        int col = c*256 + (yy&15)*16 + (xx&15);
        g_xl[gp*768 + col] = v;
    }
}

// ---------------- 2) fused patch-embed GEMM + MODE0 (vis, LN(dn), gate) ----------------
// 32 rows/block, 128 threads. Raw tokens live only in smem.
__global__ void k_pg(const float* __restrict__ bpe, const float* __restrict__ Wg_,
                     const float* __restrict__ dn_g, const float* __restrict__ dn_b,
                     const float* __restrict__ Wvis, const float* __restrict__ bvis,
                     const float* __restrict__ bgate){
    __shared__ __align__(16) float As[32][64];
    __shared__ __align__(16) float Bs[64][96];   // phase2 reuses first 32 rows
    __shared__ __align__(16) float Ts[32][96];   // tokens
    int tid = threadIdx.x;                   // 128
    int tx = tid & 15, ty = tid >> 4;        // tx 0..15, ty 0..7
    int rowbase = blockIdx.x * 32;
    int tx6 = tx*6;

    u64 acc[4][3];
    #pragma unroll
    for (int i=0;i<4;i++){ acc[i][0]=0ull; acc[i][1]=0ull; acc[i][2]=0ull; }

    const float4* Xg = reinterpret_cast<const float4*>(g_xl);
    const float4* Wg = reinterpret_cast<const float4*>(g_WpeT);
    float4* As4 = reinterpret_cast<float4*>(&As[0][0]);
    float4* Bs4 = reinterpret_cast<float4*>(&Bs[0][0]);

    // phase 1: patch GEMM (proven R10 mainloop)
    for (int kc=0; kc<12; kc++){
        #pragma unroll
        for (int r=0;r<4;r++){
            int idx = tid + 128*r;           // < 512
            int row = idx >> 4, c4 = idx & 15;
            As4[idx] = Xg[(rowbase+row)*192 + kc*16 + c4];
        }
        #pragma unroll
        for (int r=0;r<12;r++){
            int idx = tid + 128*r;           // < 1536
            int kk = idx/24, c4 = idx%24;
            Bs4[idx] = Wg[(kc*64+kk)*24 + c4];
        }
        __syncthreads();
        #pragma unroll 8
        for (int kk=0;kk<64;kk++){
            const u64* bp = reinterpret_cast<const u64*>(&Bs[kk][tx6]);
            u64 b0 = bp[0], b1 = bp[1], b2 = bp[2];
            #pragma unroll
            for (int i=0;i<4;i++){
                float a = As[ty + 8*i][kk];
                u64 ap = pack2(a, a);
                ffma2(acc[i][0], ap, b0);
                ffma2(acc[i][1], ap, b1);
                ffma2(acc[i][2], ap, b2);
            }
        }
        __syncthreads();
    }
    #pragma unroll
    for (int i=0;i<4;i++){
        int row = ty + 8*i;
        #pragma unroll
        for (int j=0;j<3;j++){
            float2 v = unpack2(acc[i][j]);
            int c = tx6 + 2*j;
            Ts[row][c]   = v.x + bpe[c];
            Ts[row][c+1] = v.y + bpe[c+1];
        }
    }
    __syncthreads();

    // phase 2: vis + LN(dn) -> g_tokens ; gate = sigmoid(LN @ W_gate + b)
    {
        int warp = tid >> 5, lane = tid & 31;
        for (int rr=0; rr<8; rr++){
            int row = warp*8 + rr;
            float v0 = Ts[row][lane], v1 = Ts[row][lane+32], v2 = Ts[row][lane+64];
            float s = v0+v1+v2;
            #pragma unroll
            for (int o=16;o;o>>=1) s += __shfl_xor_sync(0xffffffffu, s, o);
            float m = s*(1.f/96.f);
            float d0=v0-m, d1=v1-m, d2=v2-m;
            float q = d0*d0 + d1*d1 + d2*d2;
            #pragma unroll
            for (int o=16;o;o>>=1) q += __shfl_xor_sync(0xffffffffu, q, o);
            float rs = rsqrtf(q*(1.f/96.f) + 1e-5f);
            float vd = v0*Wvis[lane] + v1*Wvis[lane+32] + v2*Wvis[lane+64];
            #pragma unroll
            for (int o=16;o;o>>=1) vd += __shfl_xor_sync(0xffffffffu, vd, o);
            if (lane==0) g_vis[rowbase+row] = sigm_(vd + bvis[0]);
            float n0 = d0*rs*dn_g[lane]    + dn_b[lane];
            float n1 = d1*rs*dn_g[lane+32] + dn_b[lane+32];
            float n2 = d2*rs*dn_g[lane+64] + dn_b[lane+64];
            Ts[row][lane]=n0; Ts[row][lane+32]=n1; Ts[row][lane+64]=n2;
            float* tp = g_tokens + (rowbase+row)*96;
            tp[lane]=n0; tp[lane+32]=n1; tp[lane+64]=n2;
        }
    }

    u64 gacc[4][3];
    #pragma unroll
    for (int i=0;i<4;i++){ gacc[i][0]=0ull; gacc[i][1]=0ull; gacc[i][2]=0ull; }
    for (int kc=0;kc<3;kc++){
        __syncthreads();
        #pragma unroll
        for (int r=0;r<6;r++){
            int idx = tid + 128*r;            // < 768
            int kk = idx/24, c4 = idx%24;
            Bs4[idx] = *reinterpret_cast<const float4*>(Wg_ + (kc*32+kk)*96 + c4*4);
        }
        __syncthreads();
        #pragma unroll 8
        for (int kk=0;kk<32;kk++){
            const u64* bp = reinterpret_cast<const u64*>(&Bs[kk][tx6]);
            u64 b0 = bp[0], b1 = bp[1], b2 = bp[2];
            int kidx = kc*32 + kk;
            #pragma unroll
            for (int i=0;i<4;i++){
                float a = Ts[ty + 8*i][kidx];
                u64 ap = pack2(a, a);
                ffma2(gacc[i][0], ap, b0);
                ffma2(gacc[i][1], ap, b1);
                ffma2(gacc[i][2], ap, b2);
            }
        }
    }
    #pragma unroll
    for (int i=0;i<4;i++){
        int row = rowbase + ty + 8*i;
        #pragma unroll
        for (int j=0;j<3;j++){
            float2 v = unpack2(gacc[i][j]);
            int c = tx6 + 2*j;
            g_gate[row*96 + c]   = sigm_(v.x + bgate[c]);
            g_gate[row*96 + c+1] = sigm_(v.y + bgate[c+1]);
        }
    }
}

// ---------------- 3) row GEMM, 32-row blocks, fused LN + epilogues (R10/R14 proven) ----------------
// MODE 1: LN(ln)(tokens) @ W_in ; both halves (cb=0 -> g_xin, cb=96 -> g_zg = silu(z)*vis)
// MODE 2: (g_yg * g_zg) @ W_out ; tokens += out * gate
template<int MODE>
__global__ void k_rowgemm(const float* __restrict__ W, int wstride,
                          const float* __restrict__ lng, const float* __restrict__ lnb){
    __shared__ __align__(16) float As[32][96];
    __shared__ __align__(16) float Bs[32][96];
    int tid = threadIdx.x;                   // 128
    int tx = tid & 15, ty = tid >> 4;
    int rowbase = blockIdx.x * 32;
    int tx6 = tx*6;

    float4* As4 = reinterpret_cast<float4*>(&As[0][0]);
    float4* Bs4 = reinterpret_cast<float4*>(&Bs[0][0]);
    if (MODE == 2){
        const float4* Yg = reinterpret_cast<const float4*>(g_yg + rowbase*96);
        const float4* Zg = reinterpret_cast<const float4*>(g_zg + rowbase*96);
        #pragma unroll
        for (int r=0;r<6;r++){
            int idx = tid + 128*r;           // < 768
            float4 a = Yg[idx];
            float4 z = Zg[idx];
            a.x*=z.x; a.y*=z.y; a.z*=z.z; a.w*=z.w;
            As4[idx] = a;
        }
    } else {
        const float4* Ag = reinterpret_cast<const float4*>(g_tokens + rowbase*96);
        #pragma unroll
        for (int r=0;r<6;r++) As4[tid + 128*r] = Ag[tid + 128*r];
    }
    __syncthreads();

    if (MODE != 2){
        int warp = tid >> 5, lane = tid & 31;
        for (int rr=0; rr<8; rr++){
            int row = warp*8 + rr;
            float v0 = As[row][lane], v1 = As[row][lane+32], v2 = As[row][lane+64];
            float s = v0+v1+v2;
            #pragma unroll
            for (int o=16;o;o>>=1) s += __shfl_xor_sync(0xffffffffu, s, o);
            float m = s*(1.f/96.f);
            float d0=v0-m, d1=v1-m, d2=v2-m;
            float q = d0*d0 + d1*d1 + d2*d2;
            #pragma unroll
            for (int o=16;o;o>>=1) q += __shfl_xor_sync(0xffffffffu, q, o);
            float rs = rsqrtf(q*(1.f/96.f) + 1e-5f);
            float n0 = d0*rs*lng[lane]    + lnb[lane];
            float n1 = d1*rs*lng[lane+32] + lnb[lane+32];
            float n2 = d2*rs*lng[lane+64] + lnb[lane+64];
            As[row][lane]=n0; As[row][lane+32]=n1; As[row][lane+64]=n2;
        }
    }

    const int NHALF = (MODE==1) ? 2 : 1;
    for (int half=0; half<NHALF; half++){
        int cb = half*96;

        u64 acc[4][3];
        #pragma unroll
        for (int i=0;i<4;i++){ acc[i][0]=0ull; acc[i][1]=0ull; acc[i][2]=0ull; }

        for (int kc=0;kc<3;kc++){
            __syncthreads();
            #pragma unroll
            for (int r=0;r<6;r++){
                int idx = tid + 128*r;        // < 768
                int kk = idx/24, c4 = idx%24;
                Bs4[idx] = *reinterpret_cast<const float4*>(W + (kc*32+kk)*wstride + cb + c4*4);
            }
            __syncthreads();
            #pragma unroll 8
            for (int kk=0;kk<32;kk++){
                const u64* bp = reinterpret_cast<const u64*>(&Bs[kk][tx6]);
                u64 b0 = bp[0], b1 = bp[1], b2 = bp[2];
                int kidx = kc*32 + kk;
                #pragma unroll
                for (int i=0;i<4;i++){
                    float a = As[ty + 8*i][kidx];
                    u64 ap = pack2(a, a);
                    ffma2(acc[i][0], ap, b0);
                    ffma2(acc[i][1], ap, b1);
                    ffma2(acc[i][2], ap, b2);
                }
            }
        }

        #pragma unroll
        for (int i=0;i<4;i++){
            int row = rowbase + ty + 8*i;
            float visr = 0.f;
            if (MODE == 1 && half == 1) visr = g_vis[row];
            #pragma unroll
            for (int j=0;j<3;j++){
                float2 v = unpack2(acc[i][j]);
                int c = tx6 + 2*j;
                if (MODE == 1){
                    if (half == 0){
                        g_xin[row*96 + c]   = v.x;
                        g_xin[row*96 + c+1] = v.y;
                    } else {
                        g_zg[row*96 + c]   = silu_(v.x)*visr;
                        g_zg[row*96 + c+1] = silu_(v.y)*visr;
                    }
                } else {
                    g_tokens[row*96 + c]   += v.x * g_gate[row*96 + c];
                    g_tokens[row*96 + c+1] += v.y * g_gate[row*96 + c+1];
                }
            }
        }
    }
}

// ---------------- 4) conv1d+silu + proj (j-pair FFMA2) + dt + meta2 (R14 proven) ----------------
__global__ void k_cpd(const float* __restrict__ cw,
                      const float* __restrict__ Wx, const float* __restrict__ Wdt,
                      const float* __restrict__ bdt){
    __shared__ __align__(16) u64   xsD[32*97];   // duplicated silu(conv) pairs
    __shared__ __align__(16) float Wxs[96*38];
    __shared__ __align__(16) float prs[32*10];   // dt_raw, pitch 10
    __shared__ float cws[288];
    __shared__ float wdts[6*96];
    __shared__ float bdts[96];
    int tid = threadIdx.x;                   // 128
    int tb  = blockIdx.x * 32;
    int tt0 = tb % NT;

    for (int idx=tid; idx<96*38; idx+=128) Wxs[idx] = Wx[idx];
    for (int idx=tid; idx<6*96;  idx+=128) wdts[idx] = Wdt[idx];
    if (tid < 96){
        cws[tid] = cw[tid*3+0]; cws[96+tid] = cw[tid*3+1]; cws[192+tid] = cw[tid*3+2];
        bdts[tid] = bdt[tid];
    }
    __syncthreads();

    for (int idx=tid; idx<32*96; idx+=128){
        int l = idx/96, d = idx%96;
        int t = tt0 + l;
        const float* xp = g_xin + (tb + l)*96 + d;
        float v = xp[0]*cws[192+d];
        if (t >= 1) v = fmaf(xp[-96],  cws[96+d], v);
        if (t >= 2) v = fmaf(xp[-192], cws[d],    v);
        float s = silu_(v);
        xsD[l*97 + d] = pack2(s, s);
    }
    __syncthreads();

    {
        int tp = tid & 15;
        int jpg = tid >> 4;                  // 0..7
        u64 acc[2][3] = {{0ull,0ull,0ull},{0ull,0ull,0ull}};
        const u64* x0 = &xsD[(2*tp)*97];
        const u64* x1 = x0 + 97;
        bool q2 = (jpg < 3);
        #pragma unroll 4
        for (int k=0;k<96;k++){
            u64 a0 = x0[k];
            u64 a1 = x1[k];
            const float* wr = &Wxs[k*38];
            u64 w0 = *reinterpret_cast<const u64*>(wr + 2*jpg);
            u64 w1 = *reinterpret_cast<const u64*>(wr + 2*jpg + 16);
            ffma2(acc[0][0], a0, w0);
            ffma2(acc[1][0], a1, w0);
            ffma2(acc[0][1], a0, w1);
            ffma2(acc[1][1], a1, w1);
            if (q2){
                u64 w2 = *reinterpret_cast<const u64*>(wr + 2*jpg + 32);
                ffma2(acc[0][2], a0, w2);
                ffma2(acc[1][2], a1, w2);
            }
        }
        #pragma unroll
        for (int t=0;t<2;t++){
            int tok = 2*tp + t;
            int row = tb + tok;
            #pragma unroll
            for (int q=0;q<3;q++){
                int jp = jpg + 8*q;
                if (jp < 19){
                    float2 v = unpack2(acc[t][q]);
                    int j = 2*jp;
                    if (j < 6){
                        prs[tok*10 + j]   = v.x;
                        prs[tok*10 + j+1] = v.y;
                    } else {
                        *reinterpret_cast<float2*>(&g_bc[row*32 + (j-6)]) = v;
                    }
                }
            }
        }
    }
    __syncthreads();

    const float* xsF = reinterpret_cast<const float*>(xsD);
    for (int idx=tid; idx<32*96; idx+=128){
        int l = idx/96, d = idx%96;
        float a = bdts[d];
        #pragma unroll
        for (int r=0;r<6;r++) a = fmaf(prs[l*10+r], wdts[r*96+d], a);
        float dt = softplus_(a);
        float xs = xsF[(l*97 + d)*2];
        g_meta[(tb+l)*96 + d] = make_float2(dt, xs);
    }
}

// ---------------- 5) selective scan v2: smem-staged 64-step chunks (R14 proven) ----------------
__global__ void k_scan(const float* __restrict__ Alog, const float* __restrict__ Dp){
    __shared__ __align__(16) float2 ms[64*16];   // meta {dt, xs} for 64 t x 16 d
    __shared__ __align__(16) float  bs[64*32];   // B|C for 64 t
    __shared__ float ys[64*16];                  // outputs
    int tid  = threadIdx.x;
    int b    = blockIdx.x / 6;
    int dgrp = blockIdx.x % 6;
    int w    = tid >> 5;
    int lane = tid & 31;
    int g    = lane >> 3;
    int sl   = lane & 7;
    int s0   = 2*sl;
    int dl   = w*4 + g;                      // 0..15
    int d    = dgrp*16 + dl;

    float A0 = -__expf(Alog[d*DS + s0]);
    float A1 = -__expf(Alog[d*DS + s0 + 1]);
    float Dd = Dp[d];
    float h0 = 0.f, h1 = 0.f;

    const float2* mg = g_meta + (size_t)b*NT*DI + dgrp*16;
    const float*  bg = g_bc   + (size_t)b*NT*32;
    float*        yg = g_yg   + (size_t)b*NT*DI + dgrp*16;

    for (int c=0;c<9;c++){
        int t0 = c*64;
        #pragma unroll
        for (int r=0;r<8;r++){
            int i = tid + 128*r;             // < 1024
            int tt = i >> 4, dd = i & 15;
            ms[i] = mg[(t0+tt)*96 + dd];
        }
        #pragma unroll
        for (int r=0;r<4;r++){
            int i = tid + 128*r;             // < 512
            int tt = i >> 3, q = i & 7;
            *reinterpret_cast<float4*>(&bs[tt*32 + q*4]) =
                *reinterpret_cast<const float4*>(&bg[(t0+tt)*32 + q*4]);
        }
        __syncthreads();
        #pragma unroll 4
        for (int tt=0; tt<64; tt++){
            float2 m  = ms[tt*16 + dl];
            float2 Bv = *reinterpret_cast<const float2*>(&bs[tt*32 + s0]);
            float2 Cv = *reinterpret_cast<const float2*>(&bs[tt*32 + 16 + s0]);
            float u  = m.x * m.y;
            float e0 = __expf(m.x * A0);
            float e1 = __expf(m.x * A1);
            h0 = fmaf(e0, h0, u * Bv.x);
            h1 = fmaf(e1, h1, u * Bv.y);
            float yp = fmaf(h1, Cv.y, h0 * Cv.x);
            yp += __shfl_xor_sync(0xffffffffu, yp, 1);
            yp += __shfl_xor_sync(0xffffffffu, yp, 2);
            yp += __shfl_xor_sync(0xffffffffu, yp, 4);
            if (sl == 0) ys[tt*16 + dl] = fmaf(Dd, m.y, yp);
        }
        __syncthreads();
        #pragma unroll
        for (int r=0;r<8;r++){
            int i = tid + 128*r;             // < 1024
            int tt = i >> 4, dd = i & 15;
            yg[(t0+tt)*96 + dd] = ys[i];
        }
    }
}

// ---------------- 6) heads: depthwise 3x3 + BN + silu + three matvecs ----------------
__global__ void k_final(const float* __restrict__ hd,
                        const float* __restrict__ bng, const float* __restrict__ bnb,
                        const float* __restrict__ bnm, const float* __restrict__ bnv,
                        const float* __restrict__ Wheat, const float* __restrict__ bheat,
                        const float* __restrict__ Woff,  const float* __restrict__ boff,
                        const float* __restrict__ Wsize, const float* __restrict__ bsize,
                        float* __restrict__ out){
    __shared__ float fr[3][HP][97];
    __shared__ float gs[HP][97];
    int tid = threadIdx.x;
    int b = blockIdx.x / HP;
    int h = blockIdx.x % HP;

    for (int idx=tid; idx<3*HP*96; idx+=128){
        int r = idx/(HP*96);
        int rem = idx - r*HP*96;
        int wq = rem/96, d = rem%96;
        int hh = h - 1 + r;
        fr[r][wq][d] = (hh>=0 && hh<HP) ? g_tokens[(b*NT + hh*HP + wq)*DM + d] : 0.f;
    }
    __syncthreads();

    for (int idx=tid; idx<HP*96; idx+=128){
        int wq = idx/96, d = idx%96;
        float a = 0.f;
        #pragma unroll
        for (int i=0;i<3;i++)
            #pragma unroll
            for (int j=0;j<3;j++){
                int ww = wq - 1 + j;
                if (ww>=0 && ww<HP) a = fmaf(fr[i][ww][d], hd[d*9 + i*3 + j], a);
            }
        a = (a - bnm[d]) * rsqrtf(bnv[d] + 1e-5f);
        gs[wq][d] = silu_(a*bng[d] + bnb[d]);
    }
    __syncthreads();

    const int HEAT_OFF = 0;
    const int OFF_OFF  = NB*5*NT;
    const int SIZE_OFF = OFF_OFF + NB*2*NT;
    for (int idx=tid; idx<HP*9; idx+=128){
        int wq = idx/9, o = idx%9;
        if (o < 5){
            float a = bheat[o];
            #pragma unroll 8
            for (int d=0; d<96; d++) a = fmaf(gs[wq][d], Wheat[o*96+d], a);
            out[HEAT_OFF + ((b*5+o)*HP + h)*HP + wq] = a;
        } else if (o < 7){
            int oo = o-5;
            float a = boff[oo];
            #pragma unroll 8
            for (int d=0; d<96; d++) a = fmaf(fr[1][wq][d], Woff[oo*96+d], a);
            out[OFF_OFF + ((b*2+oo)*HP + h)*HP + wq] = a;
        } else {
            int oo = o-7;
            float a = bsize[oo];
            #pragma unroll 8
            for (int d=0; d<96; d++) a = fmaf(fr[1][wq][d], Wsize[oo*96+d], a);
            out[SIZE_OFF + ((b*2+oo)*HP + h)*HP + wq] = a;
        }
    }
}

// ---------------- launch ----------------
extern "C" void kernel_launch(void* const* d_in, const int* in_sizes, int n_in,
                              void* d_out, int out_size){
    const float* x      = (const float*)d_in[0];
    const float* W_pe   = (const float*)d_in[1];
    const float* b_pe   = (const float*)d_in[2];
    const float* W_vis  = (const float*)d_in[3];
    const float* b_vis  = (const float*)d_in[4];
    const float* dn_g   = (const float*)d_in[5];
    const float* dn_b   = (const float*)d_in[6];
    const float* W_gate = (const float*)d_in[7];
    const float* b_gate = (const float*)d_in[8];
    const float* ln_g   = (const float*)d_in[9];
    const float* ln_b   = (const float*)d_in[10];
    const float* W_in   = (const float*)d_in[11];
    const float* conv_w = (const float*)d_in[12];
    const float* W_xprj = (const float*)d_in[13];
    const float* W_dt   = (const float*)d_in[14];
    const float* b_dt   = (const float*)d_in[15];
    const float* A_log  = (const float*)d_in[16];
    const float* Dp     = (const float*)d_in[17];
    const float* W_out  = (const float*)d_in[18];
    const float* hd_dw  = (const float*)d_in[19];
    const float* bn_g   = (const float*)d_in[20];
    const float* bn_b   = (const float*)d_in[21];
    const float* bn_m   = (const float*)d_in[22];
    const float* bn_v   = (const float*)d_in[23];
    const float* W_heat = (const float*)d_in[24];
    const float* b_heat = (const float*)d_in[25];
    const float* W_off  = (const float*)d_in[26];
    const float* b_off  = (const float*)d_in[27];
    const float* W_size = (const float*)d_in[28];
    const float* b_size = (const float*)d_in[29];
    float* out = (float*)d_out;

    k_blur<<<NBLUR + 29, 256>>>(x, W_pe);
    k_pg<<<NR/32, 128>>>(b_pe, W_gate, dn_g, dn_b, W_vis, b_vis, b_gate);

    for (int rep=0; rep<4; rep++){
        k_rowgemm<1><<<NR/32, 128>>>(W_in, 192, ln_g, ln_b);
        k_cpd<<<NR/32, 128>>>(conv_w, W_xprj, W_dt, b_dt);
        k_scan<<<NB*6, 128>>>(A_log, Dp);
        k_rowgemm<2><<<NR/32, 128>>>(W_out, 96, nullptr, nullptr);
    }

    k_final<<<NB*HP, 128>>>(hd_dw, bn_g, bn_b, bn_m, bn_v,
                            W_heat, b_heat, W_off, b_off, W_size, b_size, out);
}

// round 16
// speedup vs baseline: 1.0644x; 1.0644x over previous
#include <cuda_runtime.h>
#include <math.h>

#define NB   64
#define IMG  384
#define CIN  3
#define PS   16
#define DM   96
#define DS   16
#define DI   96
#define HP   24
#define NT   576
#define NR   (NB*NT)          // 36864 token rows
#define NPIX (NB*CIN*IMG*IMG) // 28311552

// ---------------- scratch (device globals; no allocs allowed) ----------------
static __device__ float  g_xl[NPIX];        // preprocessed image, PATCH-MAJOR [gp][768]
static __device__ float  g_WpeT[768*96];    // transposed patch weights [k][d]
static __device__ float  g_tokens[NR*DM];
static __device__ float  g_vis[NR];
static __device__ float  g_gate[NR*DM];
static __device__ float  g_xin[NR*DI];      // pre-conv x branch
static __device__ float  g_zg[NR*DI];       // silu(z)*vis
static __device__ float  g_bc[NR*32];       // B(16) | C(16)
static __device__ float2 g_meta[NR*DI];     // {dt, xs}
static __device__ float  g_yg[NR*DI];       // y_raw = yp + D*xs  (zg applied in rg2)

__device__ __forceinline__ float sigm_(float x){ return 1.f/(1.f+__expf(-x)); }
__device__ __forceinline__ float silu_(float x){ return x/(1.f+__expf(-x)); }
__device__ __forceinline__ float softplus_(float x){ return (x>20.f)? x : __logf(1.f+__expf(x)); }

// ---- packed fp32x2 helpers (Blackwell FFMA2 path, PTX-only) ----
typedef unsigned long long u64;
__device__ __forceinline__ void ffma2(u64 &d, u64 a, u64 b){
    asm("fma.rn.f32x2 %0, %1, %2, %3;" : "=l"(d) : "l"(a), "l"(b), "l"(d));
}
__device__ __forceinline__ u64 pack2(float x, float y){
    u64 r;
    asm("mov.b64 %0, {%1, %2};" : "=l"(r) : "r"(__float_as_uint(x)), "r"(__float_as_uint(y)));
    return r;
}
__device__ __forceinline__ float2 unpack2(u64 v){
    unsigned lo, hi;
    asm("mov.b64 {%0, %1}, %2;" : "=r"(lo), "=r"(hi) : "l"(v));
    return make_float2(__uint_as_float(lo), __uint_as_float(hi));
}

// ---------------- 0) transpose W_pe once ----------------
__global__ void k_wt(const float* __restrict__ Wpe){
    int idx = blockIdx.x*blockDim.x + threadIdx.x;
    if (idx < 768*96){
        int k = idx/96, d = idx%96;
        g_WpeT[idx] = Wpe[d*768 + k];
    }
}

// ---------------- 1) fused 5x5 box blur + log contrast (smem tiles) ----------------
__global__ void k_blur(const float* __restrict__ x){
    __shared__ float in_s[36][37];
    __shared__ float hs[36][33];
    int tid = threadIdx.x;                   // 256
    int p = blockIdx.x / 144;                // plane = b*3 + c
    int t = blockIdx.x % 144;
    int y0 = (t/12)*32, x0 = (t%12)*32;
    const float* xp = x + (size_t)p*IMG*IMG;

    for (int idx=tid; idx<36*36; idx+=256){
        int r = idx/36, cc = idx%36;
        int yy = y0-2+r, xx = x0-2+cc;
        in_s[r][cc] = (yy>=0 && yy<IMG && xx>=0 && xx<IMG) ? xp[yy*IMG+xx] : 0.f;
    }
    __syncthreads();
    for (int idx=tid; idx<36*32; idx+=256){
        int r = idx/32, j = idx%32;
        hs[r][j] = in_s[r][j]+in_s[r][j+1]+in_s[r][j+2]+in_s[r][j+3]+in_s[r][j+4];
    }
    __syncthreads();
    int b = p/3, c = p%3;
    for (int idx=tid; idx<32*32; idx+=256){
        int r = idx/32, j = idx%32;
        float bl = (hs[r][j]+hs[r+1][j]+hs[r+2][j]+hs[r+3][j]+hs[r+4][j])*(1.f/25.f);
        float xv = in_s[r+2][j+2];
        float v  = __logf(1.f + fmaxf(xv,0.f)) - __logf(1.f + fmaxf(bl,0.f));
        int yy = y0+r, xx = x0+j;
        int gp  = b*NT + (yy>>4)*HP + (xx>>4);
        int col = c*256 + (yy&15)*16 + (xx&15);
        g_xl[gp*768 + col] = v;
    }
}

// ---------------- 2) patch embed GEMM, 32-row blocks (R14 proven) ----------------
__global__ void k_patch(const float* __restrict__ bpe){
    __shared__ __align__(16) float As[32][64];
    __shared__ __align__(16) float Bs[64][96];
    int tid = threadIdx.x;                   // 128
    int tx = tid & 15, ty = tid >> 4;        // tx 0..15 (3 u64 cols), ty 0..7
    int rowbase = blockIdx.x * 32;
    int tx6 = tx*6;

    u64 acc[4][3];
    #pragma unroll
    for (int i=0;i<4;i++){ acc[i][0]=0ull; acc[i][1]=0ull; acc[i][2]=0ull; }

    const float4* Xg = reinterpret_cast<const float4*>(g_xl);
    const float4* Wg = reinterpret_cast<const float4*>(g_WpeT);
    float4* As4 = reinterpret_cast<float4*>(&As[0][0]);
    float4* Bs4 = reinterpret_cast<float4*>(&Bs[0][0]);

    for (int kc=0; kc<12; kc++){
        #pragma unroll
        for (int r=0;r<4;r++){
            int idx = tid + 128*r;           // < 512
            int row = idx >> 4, c4 = idx & 15;
            As4[idx] = Xg[(rowbase+row)*192 + kc*16 + c4];
        }
        #pragma unroll
        for (int r=0;r<12;r++){
            int idx = tid + 128*r;           // < 1536
            int kk = idx/24, c4 = idx%24;
            Bs4[idx] = Wg[(kc*64+kk)*24 + c4];
        }
        __syncthreads();
        #pragma unroll 8
        for (int kk=0;kk<64;kk++){
            const u64* bp = reinterpret_cast<const u64*>(&Bs[kk][tx6]);
            u64 b0 = bp[0], b1 = bp[1], b2 = bp[2];
            #pragma unroll
            for (int i=0;i<4;i++){
                float a = As[ty + 8*i][kk];
                u64 ap = pack2(a, a);
                ffma2(acc[i][0], ap, b0);
                ffma2(acc[i][1], ap, b1);
                ffma2(acc[i][2], ap, b2);
            }
        }
        __syncthreads();
    }
    #pragma unroll
    for (int i=0;i<4;i++){
        int row = rowbase + ty + 8*i;
        #pragma unroll
        for (int j=0;j<3;j++){
            float2 v = unpack2(acc[i][j]);
            int c = tx6 + 2*j;
            g_tokens[row*DM + c]   = v.x + bpe[c];
            g_tokens[row*DM + c+1] = v.y + bpe[c+1];
        }
    }
}

// ---------------- 3) row GEMM, 32-row blocks, fused LN + epilogues (R14 proven) ----------------
// MODE 0: raw tokens -> vis ; LN(dn) written back ; gate = sigmoid(LN @ W_gate + b)
// MODE 1: LN(ln)(tokens) @ W_in ; both halves (cb=0 -> g_xin, cb=96 -> g_zg = silu(z)*vis)
// MODE 2: (g_yg * g_zg) @ W_out ; tokens += out * gate
template<int MODE>
__global__ void k_rowgemm(const float* __restrict__ W, int wstride,
                          const float* __restrict__ lng, const float* __restrict__ lnb,
                          const float* __restrict__ Wvis, const float* __restrict__ bvis,
                          const float* __restrict__ bgate){
    __shared__ __align__(16) float As[32][96];
    __shared__ __align__(16) float Bs[32][96];
    int tid = threadIdx.x;                   // 128
    int tx = tid & 15, ty = tid >> 4;
    int rowbase = blockIdx.x * 32;
    int tx6 = tx*6;

    float4* As4 = reinterpret_cast<float4*>(&As[0][0]);
    float4* Bs4 = reinterpret_cast<float4*>(&Bs[0][0]);
    if (MODE == 2){
        const float4* Yg = reinterpret_cast<const float4*>(g_yg + rowbase*96);
        const float4* Zg = reinterpret_cast<const float4*>(g_zg + rowbase*96);
        #pragma unroll
        for (int r=0;r<6;r++){
            int idx = tid + 128*r;           // < 768
            float4 a = Yg[idx];
            float4 z = Zg[idx];
            a.x*=z.x; a.y*=z.y; a.z*=z.z; a.w*=z.w;
            As4[idx] = a;
        }
    } else {
        const float4* Ag = reinterpret_cast<const float4*>(g_tokens + rowbase*96);
        #pragma unroll
        for (int r=0;r<6;r++) As4[tid + 128*r] = Ag[tid + 128*r];
    }
    __syncthreads();

    if (MODE != 2){
        int warp = tid >> 5, lane = tid & 31;
        for (int rr=0; rr<8; rr++){
            int row = warp*8 + rr;
            float v0 = As[row][lane], v1 = As[row][lane+32], v2 = As[row][lane+64];
            float s = v0+v1+v2;
            #pragma unroll
            for (int o=16;o;o>>=1) s += __shfl_xor_sync(0xffffffffu, s, o);
            float m = s*(1.f/96.f);
            float d0=v0-m, d1=v1-m, d2=v2-m;
            float q = d0*d0 + d1*d1 + d2*d2;
            #pragma unroll
            for (int o=16;o;o>>=1) q += __shfl_xor_sync(0xffffffffu, q, o);
            float rs = rsqrtf(q*(1.f/96.f) + 1e-5f);
            if (MODE == 0){
                float vd = v0*Wvis[lane] + v1*Wvis[lane+32] + v2*Wvis[lane+64];
                #pragma unroll
                for (int o=16;o;o>>=1) vd += __shfl_xor_sync(0xffffffffu, vd, o);
                if (lane==0) g_vis[rowbase+row] = sigm_(vd + bvis[0]);
            }
            float n0 = d0*rs*lng[lane]    + lnb[lane];
            float n1 = d1*rs*lng[lane+32] + lnb[lane+32];
            float n2 = d2*rs*lng[lane+64] + lnb[lane+64];
            As[row][lane]=n0; As[row][lane+32]=n1; As[row][lane+64]=n2;
            if (MODE == 0){
                float* tp = g_tokens + (rowbase+row)*96;
                tp[lane]=n0; tp[lane+32]=n1; tp[lane+64]=n2;
            }
        }
    }

    const int NHALF = (MODE==1) ? 2 : 1;
    for (int half=0; half<NHALF; half++){
        int cb = half*96;

        u64 acc[4][3];
        #pragma unroll
        for (int i=0;i<4;i++){ acc[i][0]=0ull; acc[i][1]=0ull; acc[i][2]=0ull; }

        for (int kc=0;kc<3;kc++){
            __syncthreads();
            #pragma unroll
            for (int r=0;r<6;r++){
                int idx = tid + 128*r;        // < 768
                int kk = idx/24, c4 = idx%24;
                Bs4[idx] = *reinterpret_cast<const float4*>(W + (kc*32+kk)*wstride + cb + c4*4);
            }
            __syncthreads();
            #pragma unroll 8
            for (int kk=0;kk<32;kk++){
                const u64* bp = reinterpret_cast<const u64*>(&Bs[kk][tx6]);
                u64 b0 = bp[0], b1 = bp[1], b2 = bp[2];
                int kidx = kc*32 + kk;
                #pragma unroll
                for (int i=0;i<4;i++){
                    float a = As[ty + 8*i][kidx];
                    u64 ap = pack2(a, a);
                    ffma2(acc[i][0], ap, b0);
                    ffma2(acc[i][1], ap, b1);
                    ffma2(acc[i][2], ap, b2);
                }
            }
        }

        #pragma unroll
        for (int i=0;i<4;i++){
            int row = rowbase + ty + 8*i;
            float visr = 0.f;
            if (MODE == 1 && half == 1) visr = g_vis[row];
            #pragma unroll
            for (int j=0;j<3;j++){
                float2 v = unpack2(acc[i][j]);
                int c = tx6 + 2*j;
                if (MODE == 0){
                    g_gate[row*96 + c]   = sigm_(v.x + bgate[c]);
                    g_gate[row*96 + c+1] = sigm_(v.y + bgate[c+1]);
                } else if (MODE == 1){
                    if (half == 0){
                        g_xin[row*96 + c]   = v.x;
                        g_xin[row*96 + c+1] = v.y;
                    } else {
                        g_zg[row*96 + c]   = silu_(v.x)*visr;
                        g_zg[row*96 + c+1] = silu_(v.y)*visr;
                    }
                } else {
                    g_tokens[row*96 + c]   += v.x * g_gate[row*96 + c];
                    g_tokens[row*96 + c+1] += v.y * g_gate[row*96 + c+1];
                }
            }
        }
    }
}

// ---------------- 4) conv1d+silu + proj + dt + meta2 v2: 64 tokens, 256 threads ----------------
__global__ void __launch_bounds__(256) k_cpd(const float* __restrict__ cw,
                      const float* __restrict__ Wx, const float* __restrict__ Wdt,
                      const float* __restrict__ bdt){
    __shared__ __align__(16) float xs_s[64*97];  // silu(conv), plain floats (24.8 KB)
    __shared__ __align__(16) float Wxs[96*38];   // 14.25 KB
    __shared__ __align__(16) float prs[64*10];   // dt_raw, pitch 10
    __shared__ float cws[288];
    __shared__ float wdts[6*96];
    __shared__ float bdts[96];
    int tid = threadIdx.x;                   // 256
    int tb  = blockIdx.x * 64;
    int tt0 = tb % NT;

    for (int idx=tid; idx<96*38; idx+=256) Wxs[idx] = Wx[idx];
    for (int idx=tid; idx<6*96;  idx+=256) wdts[idx] = Wdt[idx];
    if (tid < 96){
        cws[tid] = cw[tid*3+0]; cws[96+tid] = cw[tid*3+1]; cws[192+tid] = cw[tid*3+2];
        bdts[tid] = bdt[tid];
    }
    __syncthreads();

    // conv + silu
    for (int idx=tid; idx<64*96; idx+=256){
        int l = idx/96, d = idx%96;
        int t = tt0 + l;
        const float* xp = g_xin + (tb + l)*96 + d;
        float v = xp[0]*cws[192+d];
        if (t >= 1) v = fmaf(xp[-96],  cws[96+d], v);
        if (t >= 2) v = fmaf(xp[-192], cws[d],    v);
        xs_s[l*97 + d] = silu_(v);
    }
    __syncthreads();

    // proj: [64 x 96] @ [96 x 38], j-pair packed FFMA2
    {
        int tp  = tid & 31;                  // token pair 0..31
        int jpg = tid >> 5;                  // 0..7
        u64 acc[2][3] = {{0ull,0ull,0ull},{0ull,0ull,0ull}};
        const float* x0 = &xs_s[(2*tp)*97];
        const float* x1 = x0 + 97;
        bool q2 = (jpg < 3);
        #pragma unroll 4
        for (int k=0;k<96;k++){
            float xv0 = x0[k];
            float xv1 = x1[k];
            u64 a0 = pack2(xv0, xv0);
            u64 a1 = pack2(xv1, xv1);
            const float* wr = &Wxs[k*38];
            u64 w0 = *reinterpret_cast<const u64*>(wr + 2*jpg);
            u64 w1 = *reinterpret_cast<const u64*>(wr + 2*jpg + 16);
            ffma2(acc[0][0], a0, w0);
            ffma2(acc[1][0], a1, w0);
            ffma2(acc[0][1], a0, w1);
            ffma2(acc[1][1], a1, w1);
            if (q2){
                u64 w2 = *reinterpret_cast<const u64*>(wr + 2*jpg + 32);
                ffma2(acc[0][2], a0, w2);
                ffma2(acc[1][2], a1, w2);
            }
        }
        #pragma unroll
        for (int t=0;t<2;t++){
            int tok = 2*tp + t;
            int row = tb + tok;
            #pragma unroll
            for (int q=0;q<3;q++){
                int jp = jpg + 8*q;
                if (jp < 19){
                    float2 v = unpack2(acc[t][q]);
                    int j = 2*jp;
                    if (j < 6){
                        prs[tok*10 + j]   = v.x;
                        prs[tok*10 + j+1] = v.y;
                    } else {
                        *reinterpret_cast<float2*>(&g_bc[row*32 + (j-6)]) = v;
                    }
                }
            }
        }
    }
    __syncthreads();

    // dt = softplus(dt_raw @ W_dt + b_dt), meta2 = {dt, xs}
    for (int idx=tid; idx<64*96; idx+=256){
        int l = idx/96, d = idx%96;
        float a = bdts[d];
        #pragma unroll
        for (int r=0;r<6;r++) a = fmaf(prs[l*10+r], wdts[r*96+d], a);
        float dt = softplus_(a);
        float xs = xs_s[l*97 + d];
        g_meta[(tb+l)*96 + d] = make_float2(dt, xs);
    }
}

// ---------------- 5) selective scan v2: smem-staged 64-step chunks (R14 proven) ----------------
__global__ void k_scan(const float* __restrict__ Alog, const float* __restrict__ Dp){
    __shared__ __align__(16) float2 ms[64*16];   // meta {dt, xs} for 64 t x 16 d
    __shared__ __align__(16) float  bs[64*32];   // B|C for 64 t
    __shared__ float ys[64*16];                  // outputs
    int tid  = threadIdx.x;
    int b    = blockIdx.x / 6;
    int dgrp = blockIdx.x % 6;
    int w    = tid >> 5;
    int lane = tid & 31;
    int g    = lane >> 3;
    int sl   = lane & 7;
    int s0   = 2*sl;
    int dl   = w*4 + g;                      // 0..15
    int d    = dgrp*16 + dl;

    float A0 = -__expf(Alog[d*DS + s0]);
    float A1 = -__expf(Alog[d*DS + s0 + 1]);
    float Dd = Dp[d];
    float h0 = 0.f, h1 = 0.f;

    const float2* mg = g_meta + (size_t)b*NT*DI + dgrp*16;
    const float*  bg = g_bc   + (size_t)b*NT*32;
    float*        yg = g_yg   + (size_t)b*NT*DI + dgrp*16;

    for (int c=0;c<9;c++){
        int t0 = c*64;
        #pragma unroll
        for (int r=0;r<8;r++){
            int i = tid + 128*r;             // < 1024
            int tt = i >> 4, dd = i & 15;
            ms[i] = mg[(t0+tt)*96 + dd];
        }
        #pragma unroll
        for (int r=0;r<4;r++){
            int i = tid + 128*r;             // < 512
            int tt = i >> 3, q = i & 7;
            *reinterpret_cast<float4*>(&bs[tt*32 + q*4]) =
                *reinterpret_cast<const float4*>(&bg[(t0+tt)*32 + q*4]);
        }
        __syncthreads();
        #pragma unroll 4
        for (int tt=0; tt<64; tt++){
            float2 m  = ms[tt*16 + dl];
            float2 Bv = *reinterpret_cast<const float2*>(&bs[tt*32 + s0]);
            float2 Cv = *reinterpret_cast<const float2*>(&bs[tt*32 + 16 + s0]);
            float u  = m.x * m.y;
            float e0 = __expf(m.x * A0);
            float e1 = __expf(m.x * A1);
            h0 = fmaf(e0, h0, u * Bv.x);
            h1 = fmaf(e1, h1, u * Bv.y);
            float yp = fmaf(h1, Cv.y, h0 * Cv.x);
            yp += __shfl_xor_sync(0xffffffffu, yp, 1);
            yp += __shfl_xor_sync(0xffffffffu, yp, 2);
            yp += __shfl_xor_sync(0xffffffffu, yp, 4);
            if (sl == 0) ys[tt*16 + dl] = fmaf(Dd, m.y, yp);
        }
        __syncthreads();
        #pragma unroll
        for (int r=0;r<8;r++){
            int i = tid + 128*r;             // < 1024
            int tt = i >> 4, dd = i & 15;
            yg[(t0+tt)*96 + dd] = ys[i];
        }
    }
}

// ---------------- 6) heads: depthwise 3x3 + BN + silu + three matvecs ----------------
__global__ void k_final(const float* __restrict__ hd,
                        const float* __restrict__ bng, const float* __restrict__ bnb,
                        const float* __restrict__ bnm, const float* __restrict__ bnv,
                        const float* __restrict__ Wheat, const float* __restrict__ bheat,
                        const float* __restrict__ Woff,  const float* __restrict__ boff,
                        const float* __restrict__ Wsize, const float* __restrict__ bsize,
                        float* __restrict__ out){
    __shared__ float fr[3][HP][97];
    __shared__ float gs[HP][97];
    int tid = threadIdx.x;
    int b = blockIdx.x / HP;
    int h = blockIdx.x % HP;

    for (int idx=tid; idx<3*HP*96; idx+=128){
        int r = idx/(HP*96);
        int rem = idx - r*HP*96;
        int wq = rem/96, d = rem%96;
        int hh = h - 1 + r;
        fr[r][wq][d] = (hh>=0 && hh<HP) ? g_tokens[(b*NT + hh*HP + wq)*DM + d] : 0.f;
    }
    __syncthreads();

    for (int idx=tid; idx<HP*96; idx+=128){
        int wq = idx/96, d = idx%96;
        float a = 0.f;
        #pragma unroll
        for (int i=0;i<3;i++)
            #pragma unroll
            for (int j=0;j<3;j++){
                int ww = wq - 1 + j;
                if (ww>=0 && ww<HP) a = fmaf(fr[i][ww][d], hd[d*9 + i*3 + j], a);
            }
        a = (a - bnm[d]) * rsqrtf(bnv[d] + 1e-5f);
        gs[wq][d] = silu_(a*bng[d] + bnb[d]);
    }
    __syncthreads();

    const int HEAT_OFF = 0;
    const int OFF_OFF  = NB*5*NT;
    const int SIZE_OFF = OFF_OFF + NB*2*NT;
    for (int idx=tid; idx<HP*9; idx+=128){
        int wq = idx/9, o = idx%9;
        if (o < 5){
            float a = bheat[o];
            #pragma unroll 8
            for (int d=0; d<96; d++) a = fmaf(gs[wq][d], Wheat[o*96+d], a);
            out[HEAT_OFF + ((b*5+o)*HP + h)*HP + wq] = a;
        } else if (o < 7){
            int oo = o-5;
            float a = boff[oo];
            #pragma unroll 8
            for (int d=0; d<96; d++) a = fmaf(fr[1][wq][d], Woff[oo*96+d], a);
            out[OFF_OFF + ((b*2+oo)*HP + h)*HP + wq] = a;
        } else {
            int oo = o-7;
            float a = bsize[oo];
            #pragma unroll 8
            for (int d=0; d<96; d++) a = fmaf(fr[1][wq][d], Wsize[oo*96+d], a);
            out[SIZE_OFF + ((b*2+oo)*HP + h)*HP + wq] = a;
        }
    }
}

// ---------------- launch ----------------
extern "C" void kernel_launch(void* const* d_in, const int* in_sizes, int n_in,
                              void* d_out, int out_size){
    const float* x      = (const float*)d_in[0];
    const float* W_pe   = (const float*)d_in[1];
    const float* b_pe   = (const float*)d_in[2];
    const float* W_vis  = (const float*)d_in[3];
    const float* b_vis  = (const float*)d_in[4];
    const float* dn_g   = (const float*)d_in[5];
    const float* dn_b   = (const float*)d_in[6];
    const float* W_gate = (const float*)d_in[7];
    const float* b_gate = (const float*)d_in[8];
    const float* ln_g   = (const float*)d_in[9];
    const float* ln_b   = (const float*)d_in[10];
    const float* W_in   = (const float*)d_in[11];
    const float* conv_w = (const float*)d_in[12];
    const float* W_xprj = (const float*)d_in[13];
    const float* W_dt   = (const float*)d_in[14];
    const float* b_dt   = (const float*)d_in[15];
    const float* A_log  = (const float*)d_in[16];
    const float* Dp     = (const float*)d_in[17];
    const float* W_out  = (const float*)d_in[18];
    const float* hd_dw  = (const float*)d_in[19];
    const float* bn_g   = (const float*)d_in[20];
    const float* bn_b   = (const float*)d_in[21];
    const float* bn_m   = (const float*)d_in[22];
    const float* bn_v   = (const float*)d_in[23];
    const float* W_heat = (const float*)d_in[24];
    const float* b_heat = (const float*)d_in[25];
    const float* W_off  = (const float*)d_in[26];
    const float* b_off  = (const float*)d_in[27];
    const float* W_size = (const float*)d_in[28];
    const float* b_size = (const float*)d_in[29];
    float* out = (float*)d_out;

    k_wt<<<(768*96+255)/256, 256>>>(W_pe);
    k_blur<<<192*144, 256>>>(x);
    k_patch<<<NR/32, 128>>>(b_pe);

    k_rowgemm<0><<<NR/32, 128>>>(W_gate, 96, dn_g, dn_b, W_vis, b_vis, b_gate);

    for (int rep=0; rep<4; rep++){
        k_rowgemm<1><<<NR/32, 128>>>(W_in, 192, ln_g, ln_b, nullptr, nullptr, nullptr);
        k_cpd<<<NR/64, 256>>>(conv_w, W_xprj, W_dt, b_dt);
        k_scan<<<NB*6, 128>>>(A_log, Dp);
        k_rowgemm<2><<<NR/32, 128>>>(W_out, 96, nullptr, nullptr, nullptr, nullptr, nullptr);
    }

    k_final<<<NB*HP, 128>>>(hd_dw, bn_g, bn_b, bn_m, bn_v,
                            W_heat, b_heat, W_off, b_off, W_size, b_size, out);
}